// round 14
// baseline (speedup 1.0000x reference)
#include <cuda_runtime.h>
#include <cstdint>

#define NB 16384
#define LN 50
#define NTILES (NB / 2)
#define NTHR 512
#define SA 132          // bufA row stride (floats), odd*4 -> conflict-free frags
#define SB 68           // bufB row stride

// smem float offsets
#define O_W1LO 0
#define O_W1HI 4096
#define O_A1LO 8192
#define O_A1HI 12288
#define O_W2LO 16384
#define O_W2HI 18432
#define O_A2LO 20480
#define O_A2HI 22528
#define O_B1   24576
#define O_B2   24640
#define O_AB1  24704
#define O_AB2  24768
#define O_A3   24832
#define O_R2S  24896
#define O_UBS  25216
#define O_BUFA 25344
#define O_BUFB 42240
#define O_LGP  50944
#define O_ATT  51200
#define O_RED  51328
#define SM_FLOATS 51840
#define SMEM_REQ (SM_FLOATS * 4)

static __device__ __forceinline__ uint32_t tf32r(float x) {
    uint32_t y; asm("cvt.rn.tf32.f32 %0, %1;" : "=r"(y) : "f"(x)); return y;
}
static __device__ __forceinline__ float tf32f(float x) {
    return __uint_as_float(tf32r(x));
}

static __device__ __forceinline__ void mma8(float C[4],
                                            uint32_t a0, uint32_t a1, uint32_t a2, uint32_t a3,
                                            uint32_t b0, uint32_t b1) {
    asm volatile(
        "mma.sync.aligned.m16n8k8.row.col.f32.tf32.tf32.f32 "
        "{%0,%1,%2,%3},{%4,%5,%6,%7},{%8,%9},{%0,%1,%2,%3};"
        : "+f"(C[0]), "+f"(C[1]), "+f"(C[2]), "+f"(C[3])
        : "r"(a0), "r"(a1), "r"(a2), "r"(a3), "r"(b0), "r"(b1));
}

// Warp tile: rows [rbase, rbase+16), cols [nh*32, nh*32+32), K = 8*S.
// A row-major (stride STRIDE), B split lo/hi arrays [s][n][q] (conflict-free).
template<int S, int STRIDE>
static __device__ __forceinline__ void gemm_phase(const float* __restrict__ Ab,
                                                  const float* __restrict__ Blo,
                                                  const float* __restrict__ Bhi,
                                                  int nh, int rbase, int lane,
                                                  float C[4][4]) {
    const int rq = lane >> 2, q = lane & 3;
    const float* A00 = Ab + (rbase + rq) * STRIDE + q;
    #pragma unroll
    for (int s = 0; s < S; ++s) {
        uint32_t bl[4], bh[4];
        #pragma unroll
        for (int t = 0; t < 4; ++t) {
            int nidx = s * 256 + (nh * 32 + t * 8 + rq) * 4 + q;
            bl[t] = __float_as_uint(Blo[nidx]);
            bh[t] = __float_as_uint(Bhi[nidx]);
        }
        const int k0 = 8 * s;
        uint32_t a0 = __float_as_uint(A00[k0]);
        uint32_t a1 = __float_as_uint(A00[8 * STRIDE + k0]);
        uint32_t a2 = __float_as_uint(A00[k0 + 4]);
        uint32_t a3 = __float_as_uint(A00[8 * STRIDE + k0 + 4]);
        #pragma unroll
        for (int t = 0; t < 4; ++t)
            mma8(C[t], a0, a1, a2, a3, bl[t], bh[t]);
    }
}

// relu(C + bias) -> tf32 -> row-major float2 stores
template<int STRIDE>
static __device__ __forceinline__ void epi_store(float* __restrict__ dst,
                                                 const float C[4][4],
                                                 int nh, int rbase, int lane,
                                                 const float* __restrict__ bias) {
    const int rq = lane >> 2, q2 = 2 * (lane & 3);
    const int r0 = rbase + rq;
    #pragma unroll
    for (int t = 0; t < 4; ++t) {
        int c = nh * 32 + t * 8 + q2;
        float2 v0 = {tf32f(fmaxf(C[t][0] + bias[c],     0.f)),
                     tf32f(fmaxf(C[t][1] + bias[c + 1], 0.f))};
        float2 v1 = {tf32f(fmaxf(C[t][2] + bias[c],     0.f)),
                     tf32f(fmaxf(C[t][3] + bias[c + 1], 0.f))};
        *(float2*)&dst[r0 * STRIDE + c]       = v0;
        *(float2*)&dst[(r0 + 8) * STRIDE + c] = v1;
    }
}

#define CZERO(C) do { \
    _Pragma("unroll") for (int _t = 0; _t < 4; ++_t) \
    _Pragma("unroll") for (int _e = 0; _e < 4; ++_e) C[_t][_e] = 0.f; \
} while (0)

__global__ __launch_bounds__(NTHR, 1)
void uv_agg_mma(const int* __restrict__ nodes,
                const int* __restrict__ hist_uv,
                const int* __restrict__ hist_r,
                const float* __restrict__ v2e,
                const float* __restrict__ u2e,
                const float* __restrict__ r2e,
                const float* __restrict__ w1,
                const float* __restrict__ b1,
                const float* __restrict__ w2,
                const float* __restrict__ b2,
                const float* __restrict__ a1,
                const float* __restrict__ ab1,
                const float* __restrict__ a2,
                const float* __restrict__ ab2,
                const float* __restrict__ a3,
                const float* __restrict__ ab3,
                float* __restrict__ out)
{
    extern __shared__ __align__(16) float sm[];
    float* w1lo = sm + O_W1LO;
    float* w1hi = sm + O_W1HI;
    float* a1lo = sm + O_A1LO;
    float* a1hi = sm + O_A1HI;
    float* w2lo = sm + O_W2LO;
    float* w2hi = sm + O_W2HI;
    float* a2lo = sm + O_A2LO;
    float* a2hi = sm + O_A2HI;
    float* b1s  = sm + O_B1;
    float* b2s  = sm + O_B2;
    float* ab1s = sm + O_AB1;
    float* ab2s = sm + O_AB2;
    float* a3s  = sm + O_A3;
    float* r2s  = sm + O_R2S;
    float* ubS  = sm + O_UBS;
    float* bufA = sm + O_BUFA;   // 128 x SA (X = [e_uv|e_r], later [O|U])
    float* bufB = sm + O_BUFB;   // 128 x SB (X1, later H1)
    float* lgp  = sm + O_LGP;
    float* att  = sm + O_ATT;
    float* red  = sm + O_RED;

    const int tid  = threadIdx.x;
    const int wid  = tid >> 5;
    const int lane = tid & 31;

    // ---- stage weights: split lo/hi [s][n][q]: lo = W[8s+q][n], hi = W[8s+4+q][n] ----
    for (int i = tid; i < 4096; i += NTHR) {
        int s = i >> 8, n = (i >> 2) & 63, qq = i & 3;
        w1lo[i] = tf32f(w1[(8 * s + qq) * 64 + n]);
        w1hi[i] = tf32f(w1[(8 * s + 4 + qq) * 64 + n]);
        a1lo[i] = tf32f(a1[(8 * s + qq) * 64 + n]);
        a1hi[i] = tf32f(a1[(8 * s + 4 + qq) * 64 + n]);
    }
    for (int i = tid; i < 2048; i += NTHR) {
        int s = i >> 8, n = (i >> 2) & 63, qq = i & 3;
        w2lo[i] = tf32f(w2[(8 * s + qq) * 64 + n]);
        w2hi[i] = tf32f(w2[(8 * s + 4 + qq) * 64 + n]);
        a2lo[i] = tf32f(a2[(8 * s + qq) * 64 + n]);
        a2hi[i] = tf32f(a2[(8 * s + 4 + qq) * 64 + n]);
    }
    if (tid < 64) {
        b1s[tid]  = b1[tid];
        b2s[tid]  = b2[tid];
        ab1s[tid] = ab1[tid];
        ab2s[tid] = ab2[tid];
        a3s[tid]  = a3[tid];
    }
    for (int i = tid; i < 5 * 64; i += NTHR) r2s[i] = tf32f(r2e[i]);
    const float ab3v = ab3[0];
    __syncthreads();

    const int nh    = wid >> 3;        // col half 0/1
    const int rbase = (wid & 7) * 16;  // 16 rows per warp
    float C[4][4];

    // gather indexing: thread -> (row, quarter)
    const int gr = tid >> 2;           // row 0..127
    const int gq = tid & 3;            // quarter 0..3
    const int gbs = gr >> 6;
    const int glraw = gr & 63;
    const int gl = (glraw < LN) ? glraw : (LN - 1);

    for (int tile = blockIdx.x; tile < NTILES; tile += gridDim.x) {
        const int b0 = tile * 2;

        // ---- gather: u rows -> ubS; X = [e_uv | e_r] -> bufA row-major ----
        if (tid < 128) {
            int qb = tid >> 6;
            ubS[qb * 64 + (tid & 63)] = tf32f(u2e[(size_t)nodes[b0 + qb] * 64 + (tid & 63)]);
        }
        {
            float* dst = bufA + gr * SA;
            if (gq < 2) {   // e_uv cols gq*32 .. gq*32+31
                int uv = hist_uv[(b0 + gbs) * LN + gl];
                const float4* vp = (const float4*)(v2e + (size_t)uv * 64) + gq * 8;
                #pragma unroll
                for (int j = 0; j < 8; ++j) {
                    float4 f = vp[j];
                    float4 g = {tf32f(f.x), tf32f(f.y), tf32f(f.z), tf32f(f.w)};
                    *(float4*)&dst[gq * 32 + 4 * j] = g;
                }
            } else {        // e_r cols 64 + (gq-2)*32 ..
                int rv = hist_r[(b0 + gbs) * LN + gl];
                int rr = (rv > 0) ? (rv - 1) : ((rv < 0) ? (rv + 1) : 0);
                const float4* rp = (const float4*)(r2s + rr * 64) + (gq - 2) * 8;
                #pragma unroll
                for (int j = 0; j < 8; ++j)
                    *(float4*)&dst[64 + (gq - 2) * 32 + 4 * j] = rp[j];
            }
        }
        __syncthreads();

        // ---- GEMM1: X1 = relu(X @ W1 + b1) -> bufB ----
        CZERO(C);
        gemm_phase<16, SA>(bufA, w1lo, w1hi, nh, rbase, lane, C);
        epi_store<SB>(bufB, C, nh, rbase, lane, b1s);
        {   // stage U into bufA cols 64..127 (16 cols per thread)
            const float4* up = (const float4*)(ubS + gbs * 64) + gq * 4;
            float* dst = bufA + gr * SA + 64 + gq * 16;
            #pragma unroll
            for (int j = 0; j < 4; ++j)
                *(float4*)&dst[4 * j] = up[j];
        }
        __syncthreads();

        // ---- GEMM2: O = relu(X1 @ W2 + b2) -> bufA cols 0..63 ----
        CZERO(C);
        gemm_phase<8, SB>(bufB, w2lo, w2hi, nh, rbase, lane, C);
        epi_store<SA>(bufA, C, nh, rbase, lane, b2s);
        __syncthreads();

        // ---- GEMM3: H1 = relu([O|U] @ A1 + ab1) -> bufB ----
        CZERO(C);
        gemm_phase<16, SA>(bufA, a1lo, a1hi, nh, rbase, lane, C);
        epi_store<SB>(bufB, C, nh, rbase, lane, ab1s);
        __syncthreads();

        // ---- GEMM4: H2 = relu(H1 @ A2 + ab2); logit partials = H2 . a3 ----
        CZERO(C);
        gemm_phase<8, SB>(bufB, a2lo, a2hi, nh, rbase, lane, C);
        {
            const int rq = lane >> 2, q2 = 2 * (lane & 3);
            float pa = 0.f, pb = 0.f;   // rows rbase+rq, rbase+rq+8
            #pragma unroll
            for (int t = 0; t < 4; ++t) {
                int c = nh * 32 + t * 8 + q2;
                pa += fmaxf(C[t][0] + ab2s[c],     0.f) * a3s[c];
                pa += fmaxf(C[t][1] + ab2s[c + 1], 0.f) * a3s[c + 1];
                pb += fmaxf(C[t][2] + ab2s[c],     0.f) * a3s[c];
                pb += fmaxf(C[t][3] + ab2s[c + 1], 0.f) * a3s[c + 1];
            }
            pa += __shfl_xor_sync(~0u, pa, 1); pa += __shfl_xor_sync(~0u, pa, 2);
            pb += __shfl_xor_sync(~0u, pb, 1); pb += __shfl_xor_sync(~0u, pb, 2);
            if ((lane & 3) == 0) {
                int r0 = rbase + rq;
                lgp[nh * 128 + r0]     = pa;
                lgp[nh * 128 + r0 + 8] = pb;
            }
        }
        __syncthreads();

        // ---- softmax over 50 (warps 0,1 -> b0,b1) ----
        if (tid < 64) {
            int w = tid >> 5, ln2 = tid & 31;
            float v1 = lgp[w * 64 + ln2] + lgp[128 + w * 64 + ln2] + ab3v;
            float v2 = (ln2 + 32 < LN)
                     ? (lgp[w * 64 + ln2 + 32] + lgp[128 + w * 64 + ln2 + 32] + ab3v)
                     : -1e30f;
            float m = fmaxf(v1, v2);
            #pragma unroll
            for (int o = 16; o; o >>= 1) m = fmaxf(m, __shfl_xor_sync(~0u, m, o));
            float e1 = expf(v1 - m);
            float e2 = (ln2 + 32 < LN) ? expf(v2 - m) : 0.f;
            float s = e1 + e2;
            #pragma unroll
            for (int o = 16; o; o >>= 1) s += __shfl_xor_sync(~0u, s, o);
            float inv = 1.f / s;
            att[w * 64 + ln2] = e1 * inv;
            if (ln2 + 32 < LN) att[w * 64 + ln2 + 32] = e2 * inv;
        }
        __syncthreads();

        // ---- aggregation: out[b,d] = sum_l O[l,d]*att[l] (O row-major in bufA) ----
        {
            int bs = tid >> 8;                 // 0..1
            int k = tid & 255;
            int d = k & 63, qh = k >> 6;       // qh 0..3
            float acc = 0.f;
            for (int l = qh; l < LN; l += 4)
                acc += bufA[(bs * 64 + l) * SA + d] * att[bs * 64 + l];
            red[tid] = acc;
        }
        __syncthreads();
        if (tid < 128) {
            int bs = tid >> 6, d = tid & 63;
            out[(size_t)(b0 + bs) * 64 + d] =
                red[bs * 256 + d] + red[bs * 256 + 64 + d] +
                red[bs * 256 + 128 + d] + red[bs * 256 + 192 + d];
        }
        __syncthreads();
    }
}

extern "C" void kernel_launch(void* const* d_in, const int* in_sizes, int n_in,
                              void* d_out, int out_size)
{
    const int*   nodes = (const int*)d_in[0];
    const int*   huv   = (const int*)d_in[1];
    const int*   hr    = (const int*)d_in[2];
    const float* v2e   = (const float*)d_in[3];
    const float* u2e   = (const float*)d_in[4];
    const float* r2e   = (const float*)d_in[5];
    const float* w1    = (const float*)d_in[6];
    const float* b1    = (const float*)d_in[7];
    const float* w2    = (const float*)d_in[8];
    const float* b2    = (const float*)d_in[9];
    const float* a1    = (const float*)d_in[10];
    const float* ab1   = (const float*)d_in[11];
    const float* a2    = (const float*)d_in[12];
    const float* ab2   = (const float*)d_in[13];
    const float* a3    = (const float*)d_in[14];
    const float* ab3   = (const float*)d_in[15];
    float* out = (float*)d_out;

    cudaFuncSetAttribute(uv_agg_mma, cudaFuncAttributeMaxDynamicSharedMemorySize, SMEM_REQ);

    uv_agg_mma<<<148, NTHR, SMEM_REQ>>>(nodes, huv, hr, v2e, u2e, r2e,
                                        w1, b1, w2, b2,
                                        a1, ab1, a2, ab2, a3, ab3, out);
}

// round 15
// speedup vs baseline: 1.1966x; 1.1966x over previous
#include <cuda_runtime.h>
#include <cstdint>

#define NB 16384
#define LN 50
#define NTILES (NB / 2)
#define NTHR 256
#define SA 132          // bufA row stride (floats), odd*4 -> conflict-free frags
#define SB 68           // bufB row stride

// smem float offsets
#define O_W1P  0
#define O_A1P  8192
#define O_W2P  16384
#define O_A2P  20480
#define O_B1   24576
#define O_B2   24640
#define O_AB1  24704
#define O_AB2  24768
#define O_A3   24832
#define O_R2S  24896
#define O_UBS  25216
#define O_BUFA 25344
#define O_BUFB 42240
#define O_LGP  50944
#define O_ATT  51200
#define O_RED  51328
#define SM_FLOATS 51584
#define SMEM_REQ (SM_FLOATS * 4)

static __device__ __forceinline__ uint32_t tf32r(float x) {
    uint32_t y; asm("cvt.rn.tf32.f32 %0, %1;" : "=r"(y) : "f"(x)); return y;
}
static __device__ __forceinline__ float tf32f(float x) {
    return __uint_as_float(tf32r(x));
}

static __device__ __forceinline__ void mma8(float C[4],
                                            uint32_t a0, uint32_t a1, uint32_t a2, uint32_t a3,
                                            uint32_t b0, uint32_t b1) {
    asm volatile(
        "mma.sync.aligned.m16n8k8.row.col.f32.tf32.tf32.f32 "
        "{%0,%1,%2,%3},{%4,%5,%6,%7},{%8,%9},{%0,%1,%2,%3};"
        : "+f"(C[0]), "+f"(C[1]), "+f"(C[2]), "+f"(C[3])
        : "r"(a0), "r"(a1), "r"(a2), "r"(a3), "r"(b0), "r"(b1));
}

// Warp tile: rows [rbase, rbase+32), cols [nh*32, nh*32+32), K = 8*S.
// A row-major (stride STRIDE); B interleaved [s][n][q][(lo,hi)] -> one LDS.64
// per fragment, block-preloaded 8 k-steps at a time for deep ILP.
template<int S, int STRIDE>
static __device__ __forceinline__ void gemm_phase(const float* __restrict__ Ab,
                                                  const float* __restrict__ Bp,
                                                  int nh, int rbase, int lane,
                                                  float C[2][4][4]) {
    const int rq = lane >> 2, q = lane & 3;
    const float* A00 = Ab + (rbase + rq) * STRIDE + q;
    const float* B00 = Bp + (nh * 32 + rq) * 8 + q * 2;
    #pragma unroll
    for (int half = 0; half < S / 8; ++half) {
        // preload B fragments for 8 k-steps (32 x LDS.64 = 64 regs)
        uint2 B[8][4];
        #pragma unroll
        for (int s8 = 0; s8 < 8; ++s8)
            #pragma unroll
            for (int t = 0; t < 4; ++t)
                B[s8][t] = *(const uint2*)&B00[(half * 8 + s8) * 512 + t * 64];
        #pragma unroll
        for (int s8 = 0; s8 < 8; ++s8) {
            const int k0 = (half * 8 + s8) * 8;
            uint32_t a[2][4];
            #pragma unroll
            for (int rg = 0; rg < 2; ++rg) {
                const float* Ar = A00 + rg * 16 * STRIDE;
                a[rg][0] = __float_as_uint(Ar[k0]);
                a[rg][1] = __float_as_uint(Ar[8 * STRIDE + k0]);
                a[rg][2] = __float_as_uint(Ar[k0 + 4]);
                a[rg][3] = __float_as_uint(Ar[8 * STRIDE + k0 + 4]);
            }
            #pragma unroll
            for (int rg = 0; rg < 2; ++rg)
                #pragma unroll
                for (int t = 0; t < 4; ++t)
                    mma8(C[rg][t], a[rg][0], a[rg][1], a[rg][2], a[rg][3],
                         B[s8][t].x, B[s8][t].y);
        }
    }
}

// relu(C + bias) -> tf32 -> row-major float2 stores
template<int STRIDE>
static __device__ __forceinline__ void epi_store(float* __restrict__ dst,
                                                 const float C[2][4][4],
                                                 int nh, int rbase, int lane,
                                                 const float* __restrict__ bias) {
    const int rq = lane >> 2, q2 = 2 * (lane & 3);
    #pragma unroll
    for (int rg = 0; rg < 2; ++rg) {
        int r0 = rbase + rg * 16 + rq;
        #pragma unroll
        for (int t = 0; t < 4; ++t) {
            int c = nh * 32 + t * 8 + q2;
            float2 v0 = {tf32f(fmaxf(C[rg][t][0] + bias[c],     0.f)),
                         tf32f(fmaxf(C[rg][t][1] + bias[c + 1], 0.f))};
            float2 v1 = {tf32f(fmaxf(C[rg][t][2] + bias[c],     0.f)),
                         tf32f(fmaxf(C[rg][t][3] + bias[c + 1], 0.f))};
            *(float2*)&dst[r0 * STRIDE + c]       = v0;
            *(float2*)&dst[(r0 + 8) * STRIDE + c] = v1;
        }
    }
}

#define CZERO(C) do { \
    _Pragma("unroll") for (int _rg = 0; _rg < 2; ++_rg) \
    _Pragma("unroll") for (int _t = 0; _t < 4; ++_t) \
    _Pragma("unroll") for (int _e = 0; _e < 4; ++_e) C[_rg][_t][_e] = 0.f; \
} while (0)

__global__ __launch_bounds__(NTHR, 1)
void uv_agg_mma(const int* __restrict__ nodes,
                const int* __restrict__ hist_uv,
                const int* __restrict__ hist_r,
                const float* __restrict__ v2e,
                const float* __restrict__ u2e,
                const float* __restrict__ r2e,
                const float* __restrict__ w1,
                const float* __restrict__ b1,
                const float* __restrict__ w2,
                const float* __restrict__ b2,
                const float* __restrict__ a1,
                const float* __restrict__ ab1,
                const float* __restrict__ a2,
                const float* __restrict__ ab2,
                const float* __restrict__ a3,
                const float* __restrict__ ab3,
                float* __restrict__ out)
{
    extern __shared__ __align__(16) float sm[];
    float* w1p  = sm + O_W1P;
    float* a1p  = sm + O_A1P;
    float* w2p  = sm + O_W2P;
    float* a2p  = sm + O_A2P;
    float* b1s  = sm + O_B1;
    float* b2s  = sm + O_B2;
    float* ab1s = sm + O_AB1;
    float* ab2s = sm + O_AB2;
    float* a3s  = sm + O_A3;
    float* r2s  = sm + O_R2S;
    float* ubS  = sm + O_UBS;
    float* bufA = sm + O_BUFA;   // 128 x SA (X = [e_uv|e_r], later [O|U])
    float* bufB = sm + O_BUFB;   // 128 x SB (X1, later H1)
    float* lgp  = sm + O_LGP;
    float* att  = sm + O_ATT;
    float* red  = sm + O_RED;

    const int tid  = threadIdx.x;
    const int wid  = tid >> 5;
    const int lane = tid & 31;

    // ---- stage weights interleaved [s][n][q][h]: h=0 -> W[8s+q][n], h=1 -> W[8s+4+q][n] ----
    for (int i = tid; i < 8192; i += NTHR) {
        int s = i >> 9, rem = i & 511, n = rem >> 3, qq = (rem >> 1) & 3, h = i & 1;
        int k = 8 * s + qq + 4 * h;
        w1p[i] = tf32f(w1[k * 64 + n]);
        a1p[i] = tf32f(a1[k * 64 + n]);
    }
    for (int i = tid; i < 4096; i += NTHR) {
        int s = i >> 9, rem = i & 511, n = rem >> 3, qq = (rem >> 1) & 3, h = i & 1;
        int k = 8 * s + qq + 4 * h;
        w2p[i] = tf32f(w2[k * 64 + n]);
        a2p[i] = tf32f(a2[k * 64 + n]);
    }
    if (tid < 64) {
        b1s[tid]  = b1[tid];
        b2s[tid]  = b2[tid];
        ab1s[tid] = ab1[tid];
        ab2s[tid] = ab2[tid];
        a3s[tid]  = a3[tid];
    }
    for (int i = tid; i < 5 * 64; i += NTHR) r2s[i] = tf32f(r2e[i]);
    const float ab3v = ab3[0];
    __syncthreads();

    const int nh    = wid >> 2;
    const int rbase = (wid & 3) * 32;
    float C[2][4][4];

    for (int tile = blockIdx.x; tile < NTILES; tile += gridDim.x) {
        const int b0 = tile * 2;

        // ---- gather: u rows -> ubS; X = [e_uv | e_r] -> bufA row-major ----
        if (tid < 128) {
            int qb = tid >> 6;
            ubS[qb * 64 + (tid & 63)] = tf32f(u2e[(size_t)nodes[b0 + qb] * 64 + (tid & 63)]);
        }
        {
            int r = tid >> 1, h = tid & 1;
            int bs = r >> 6, lraw = r & 63;
            int l = (lraw < LN) ? lraw : (LN - 1);
            int uv = hist_uv[(b0 + bs) * LN + l];
            int rv = hist_r[(b0 + bs) * LN + l];
            int rr = (rv > 0) ? (rv - 1) : ((rv < 0) ? (rv + 1) : 0);
            float* dst = bufA + r * SA;
            const float4* vp = (const float4*)(v2e + (size_t)uv * 64) + h * 8;
            #pragma unroll
            for (int j = 0; j < 8; ++j) {
                float4 f = vp[j];
                float4 g = {tf32f(f.x), tf32f(f.y), tf32f(f.z), tf32f(f.w)};
                *(float4*)&dst[h * 32 + 4 * j] = g;
            }
            const float4* rp = (const float4*)(r2s + rr * 64) + h * 8;
            #pragma unroll
            for (int j = 0; j < 8; ++j)
                *(float4*)&dst[64 + h * 32 + 4 * j] = rp[j];
        }
        __syncthreads();

        // ---- GEMM1: X1 = relu(X @ W1 + b1) -> bufB ----
        CZERO(C);
        gemm_phase<16, SA>(bufA, w1p, nh, rbase, lane, C);
        epi_store<SB>(bufB, C, nh, rbase, lane, b1s);
        {   // stage U into bufA cols 64..127
            int r = tid >> 1, h = tid & 1, bs = r >> 6;
            const float4* up = (const float4*)(ubS + bs * 64) + h * 8;
            float* dst = bufA + r * SA + 64;
            #pragma unroll
            for (int j = 0; j < 8; ++j)
                *(float4*)&dst[h * 32 + 4 * j] = up[j];
        }
        __syncthreads();

        // ---- GEMM2: O = relu(X1 @ W2 + b2) -> bufA cols 0..63 ----
        CZERO(C);
        gemm_phase<8, SB>(bufB, w2p, nh, rbase, lane, C);
        epi_store<SA>(bufA, C, nh, rbase, lane, b2s);
        __syncthreads();

        // ---- GEMM3: H1 = relu([O|U] @ A1 + ab1) -> bufB ----
        CZERO(C);
        gemm_phase<16, SA>(bufA, a1p, nh, rbase, lane, C);
        epi_store<SB>(bufB, C, nh, rbase, lane, ab1s);
        __syncthreads();

        // ---- GEMM4: H2 = relu(H1 @ A2 + ab2); logit partials = H2 . a3 ----
        CZERO(C);
        gemm_phase<8, SB>(bufB, a2p, nh, rbase, lane, C);
        {
            const int rq = lane >> 2, q2 = 2 * (lane & 3);
            #pragma unroll
            for (int rg = 0; rg < 2; ++rg) {
                float pa = 0.f, pb = 0.f;
                #pragma unroll
                for (int t = 0; t < 4; ++t) {
                    int c = nh * 32 + t * 8 + q2;
                    pa += fmaxf(C[rg][t][0] + ab2s[c],     0.f) * a3s[c];
                    pa += fmaxf(C[rg][t][1] + ab2s[c + 1], 0.f) * a3s[c + 1];
                    pb += fmaxf(C[rg][t][2] + ab2s[c],     0.f) * a3s[c];
                    pb += fmaxf(C[rg][t][3] + ab2s[c + 1], 0.f) * a3s[c + 1];
                }
                pa += __shfl_xor_sync(~0u, pa, 1); pa += __shfl_xor_sync(~0u, pa, 2);
                pb += __shfl_xor_sync(~0u, pb, 1); pb += __shfl_xor_sync(~0u, pb, 2);
                if ((lane & 3) == 0) {
                    int r0 = rbase + rg * 16 + rq;
                    lgp[nh * 128 + r0]     = pa;
                    lgp[nh * 128 + r0 + 8] = pb;
                }
            }
        }
        __syncthreads();

        // ---- softmax over 50 (warps 0,1 -> b0,b1) ----
        if (tid < 64) {
            int w = tid >> 5, ln2 = tid & 31;
            float v1 = lgp[w * 64 + ln2] + lgp[128 + w * 64 + ln2] + ab3v;
            float v2 = (ln2 + 32 < LN)
                     ? (lgp[w * 64 + ln2 + 32] + lgp[128 + w * 64 + ln2 + 32] + ab3v)
                     : -1e30f;
            float m = fmaxf(v1, v2);
            #pragma unroll
            for (int o = 16; o; o >>= 1) m = fmaxf(m, __shfl_xor_sync(~0u, m, o));
            float e1 = expf(v1 - m);
            float e2 = (ln2 + 32 < LN) ? expf(v2 - m) : 0.f;
            float s = e1 + e2;
            #pragma unroll
            for (int o = 16; o; o >>= 1) s += __shfl_xor_sync(~0u, s, o);
            float inv = 1.f / s;
            att[w * 64 + ln2] = e1 * inv;
            if (ln2 + 32 < LN) att[w * 64 + ln2 + 32] = e2 * inv;
        }
        __syncthreads();

        // ---- aggregation: out[b,d] = sum_l O[l,d]*att[l] (O row-major in bufA) ----
        {
            int bs = tid >> 7, dq = tid & 127;
            int d = dq & 63, qh = dq >> 6;
            float acc = 0.f;
            for (int l = qh; l < LN; l += 2)
                acc += bufA[(bs * 64 + l) * SA + d] * att[bs * 64 + l];
            red[tid] = acc;
        }
        __syncthreads();
        if (tid < 128) {
            int bs = tid >> 6, d = tid & 63;
            out[(size_t)(b0 + bs) * 64 + d] = red[bs * 128 + d] + red[bs * 128 + 64 + d];
        }
        __syncthreads();
    }
}

extern "C" void kernel_launch(void* const* d_in, const int* in_sizes, int n_in,
                              void* d_out, int out_size)
{
    const int*   nodes = (const int*)d_in[0];
    const int*   huv   = (const int*)d_in[1];
    const int*   hr    = (const int*)d_in[2];
    const float* v2e   = (const float*)d_in[3];
    const float* u2e   = (const float*)d_in[4];
    const float* r2e   = (const float*)d_in[5];
    const float* w1    = (const float*)d_in[6];
    const float* b1    = (const float*)d_in[7];
    const float* w2    = (const float*)d_in[8];
    const float* b2    = (const float*)d_in[9];
    const float* a1    = (const float*)d_in[10];
    const float* ab1   = (const float*)d_in[11];
    const float* a2    = (const float*)d_in[12];
    const float* ab2   = (const float*)d_in[13];
    const float* a3    = (const float*)d_in[14];
    const float* ab3   = (const float*)d_in[15];
    float* out = (float*)d_out;

    cudaFuncSetAttribute(uv_agg_mma, cudaFuncAttributeMaxDynamicSharedMemorySize, SMEM_REQ);

    uv_agg_mma<<<148, NTHR, SMEM_REQ>>>(nodes, huv, hr, v2e, u2e, r2e,
                                        w1, b1, w2, b2,
                                        a1, ab1, a2, ab2, a3, ab3, out);
}

// round 16
// speedup vs baseline: 1.2195x; 1.0192x over previous
#include <cuda_runtime.h>
#include <cstdint>

#define NB 16384
#define LN 50
#define BPT 3                       // batches per tile
#define MROWS 192                   // BPT * 64
#define NT ((NB + BPT - 1) / BPT)   // 5462
#define NTHR 384
#define SA 132                      // buffer row stride (floats), 4*odd -> conflict-free

// smem float offsets
#define O_W1P  0
#define O_A1P  8192
#define O_W2P  16384
#define O_A2P  20480
#define O_B1   24576
#define O_B2   24640
#define O_AB1  24704
#define O_AB2  24768
#define O_A3   24832
#define O_R2S  24896
#define O_UBS  25216
#define O_BUF  25408
#define O_LGP  50752
#define O_ATT  51136
#define O_RED  51328
#define SM_FLOATS 51712
#define SMEM_REQ (SM_FLOATS * 4)

static __device__ __forceinline__ uint32_t tf32r(float x) {
    uint32_t y; asm("cvt.rn.tf32.f32 %0, %1;" : "=r"(y) : "f"(x)); return y;
}
static __device__ __forceinline__ float tf32f(float x) {
    return __uint_as_float(tf32r(x));
}

static __device__ __forceinline__ void mma8(float C[4],
                                            uint32_t a0, uint32_t a1, uint32_t a2, uint32_t a3,
                                            uint32_t b0, uint32_t b1) {
    asm volatile(
        "mma.sync.aligned.m16n8k8.row.col.f32.tf32.tf32.f32 "
        "{%0,%1,%2,%3},{%4,%5,%6,%7},{%8,%9},{%0,%1,%2,%3};"
        : "+f"(C[0]), "+f"(C[1]), "+f"(C[2]), "+f"(C[3])
        : "r"(a0), "r"(a1), "r"(a2), "r"(a3), "r"(b0), "r"(b1));
}

// Warp tile: rows [rbase, rbase+32), cols [nh*32, nh*32+32), K = 8*S.
// A row-major stride SA (pointer pre-offset to K-base col); B interleaved
// [s][n][q][(lo,hi)] -> one LDS.64 per fragment, block-preloaded 8 k-steps.
template<int S>
static __device__ __forceinline__ void gemm_phase(const float* __restrict__ Ab,
                                                  const float* __restrict__ Bp,
                                                  int nh, int rbase, int lane,
                                                  float C[2][4][4]) {
    const int rq = lane >> 2, q = lane & 3;
    const float* A00 = Ab + (rbase + rq) * SA + q;
    const float* B00 = Bp + (nh * 32 + rq) * 8 + q * 2;
    #pragma unroll
    for (int half = 0; half < S / 8; ++half) {
        uint2 B[8][4];
        #pragma unroll
        for (int s8 = 0; s8 < 8; ++s8)
            #pragma unroll
            for (int t = 0; t < 4; ++t)
                B[s8][t] = *(const uint2*)&B00[(half * 8 + s8) * 512 + t * 64];
        #pragma unroll
        for (int s8 = 0; s8 < 8; ++s8) {
            const int k0 = (half * 8 + s8) * 8;
            uint32_t a[2][4];
            #pragma unroll
            for (int rg = 0; rg < 2; ++rg) {
                const float* Ar = A00 + rg * 16 * SA;
                a[rg][0] = __float_as_uint(Ar[k0]);
                a[rg][1] = __float_as_uint(Ar[8 * SA + k0]);
                a[rg][2] = __float_as_uint(Ar[k0 + 4]);
                a[rg][3] = __float_as_uint(Ar[8 * SA + k0 + 4]);
            }
            #pragma unroll
            for (int rg = 0; rg < 2; ++rg)
                #pragma unroll
                for (int t = 0; t < 4; ++t)
                    mma8(C[rg][t], a[rg][0], a[rg][1], a[rg][2], a[rg][3],
                         B[s8][t].x, B[s8][t].y);
        }
    }
}

// relu(C + bias) -> tf32 -> row-major float2 stores (dst pre-offset to dest col base)
static __device__ __forceinline__ void epi_store(float* __restrict__ dst,
                                                 const float C[2][4][4],
                                                 int nh, int rbase, int lane,
                                                 const float* __restrict__ bias) {
    const int rq = lane >> 2, q2 = 2 * (lane & 3);
    #pragma unroll
    for (int rg = 0; rg < 2; ++rg) {
        int r0 = rbase + rg * 16 + rq;
        #pragma unroll
        for (int t = 0; t < 4; ++t) {
            int c = nh * 32 + t * 8 + q2;
            float2 v0 = {tf32f(fmaxf(C[rg][t][0] + bias[c],     0.f)),
                         tf32f(fmaxf(C[rg][t][1] + bias[c + 1], 0.f))};
            float2 v1 = {tf32f(fmaxf(C[rg][t][2] + bias[c],     0.f)),
                         tf32f(fmaxf(C[rg][t][3] + bias[c + 1], 0.f))};
            *(float2*)&dst[r0 * SA + c]       = v0;
            *(float2*)&dst[(r0 + 8) * SA + c] = v1;
        }
    }
}

#define CZERO(C) do { \
    _Pragma("unroll") for (int _rg = 0; _rg < 2; ++_rg) \
    _Pragma("unroll") for (int _t = 0; _t < 4; ++_t) \
    _Pragma("unroll") for (int _e = 0; _e < 4; ++_e) C[_rg][_t][_e] = 0.f; \
} while (0)

__global__ __launch_bounds__(NTHR, 1)
void uv_agg_mma(const int* __restrict__ nodes,
                const int* __restrict__ hist_uv,
                const int* __restrict__ hist_r,
                const float* __restrict__ v2e,
                const float* __restrict__ u2e,
                const float* __restrict__ r2e,
                const float* __restrict__ w1,
                const float* __restrict__ b1,
                const float* __restrict__ w2,
                const float* __restrict__ b2,
                const float* __restrict__ a1,
                const float* __restrict__ ab1,
                const float* __restrict__ a2,
                const float* __restrict__ ab2,
                const float* __restrict__ a3,
                const float* __restrict__ ab3,
                float* __restrict__ out)
{
    extern __shared__ __align__(16) float sm[];
    float* w1p  = sm + O_W1P;
    float* a1p  = sm + O_A1P;
    float* w2p  = sm + O_W2P;
    float* a2p  = sm + O_A2P;
    float* b1s  = sm + O_B1;
    float* b2s  = sm + O_B2;
    float* ab1s = sm + O_AB1;
    float* ab2s = sm + O_AB2;
    float* a3s  = sm + O_A3;
    float* r2s  = sm + O_R2S;
    float* ubS  = sm + O_UBS;
    float* buf  = sm + O_BUF;    // 192 x SA single activation buffer
    float* lgp  = sm + O_LGP;    // 2 x 192 logit partials
    float* att  = sm + O_ATT;    // 192
    float* red  = sm + O_RED;    // 384

    const int tid  = threadIdx.x;
    const int wid  = tid >> 5;
    const int lane = tid & 31;

    // ---- stage weights interleaved [s][n][q][h]: h=0 -> W[8s+q][n], h=1 -> W[8s+4+q][n] ----
    for (int i = tid; i < 8192; i += NTHR) {
        int s = i >> 9, rem = i & 511, n = rem >> 3, qq = (rem >> 1) & 3, h = i & 1;
        int k = 8 * s + qq + 4 * h;
        w1p[i] = tf32f(w1[k * 64 + n]);
        a1p[i] = tf32f(a1[k * 64 + n]);
    }
    for (int i = tid; i < 4096; i += NTHR) {
        int s = i >> 9, rem = i & 511, n = rem >> 3, qq = (rem >> 1) & 3, h = i & 1;
        int k = 8 * s + qq + 4 * h;
        w2p[i] = tf32f(w2[k * 64 + n]);
        a2p[i] = tf32f(a2[k * 64 + n]);
    }
    if (tid < 64) {
        b1s[tid]  = b1[tid];
        b2s[tid]  = b2[tid];
        ab1s[tid] = ab1[tid];
        ab2s[tid] = ab2[tid];
        a3s[tid]  = a3[tid];
    }
    for (int i = tid; i < 5 * 64; i += NTHR) r2s[i] = tf32f(r2e[i]);
    const float ab3v = ab3[0];
    __syncthreads();

    const int nh    = wid / 6;         // col half 0/1
    const int rbase = (wid % 6) * 32;  // 32 rows per warp
    float C[2][4][4];

    // gather mapping: thread -> (row, half)
    const int gr = tid >> 1;           // 0..191
    const int gh = tid & 1;
    const int gbs = gr >> 6;           // 0..2
    const int glraw = gr & 63;
    const int gl = (glraw < LN) ? glraw : (LN - 1);

    for (int tile = blockIdx.x; tile < NT; tile += gridDim.x) {
        const int b0 = tile * BPT;

        // ---- gather: u rows -> ubS; X = [e_uv | e_r] -> buf cols 0..127 ----
        if (tid < 192) {
            int qb = tid >> 6;
            int bq = b0 + qb; if (bq > NB - 1) bq = NB - 1;
            ubS[qb * 64 + (tid & 63)] = tf32f(u2e[(size_t)nodes[bq] * 64 + (tid & 63)]);
        }
        {
            int bq = b0 + gbs; if (bq > NB - 1) bq = NB - 1;
            int uv = hist_uv[bq * LN + gl];
            int rv = hist_r[bq * LN + gl];
            int rr = (rv > 0) ? (rv - 1) : ((rv < 0) ? (rv + 1) : 0);
            float* dst = buf + gr * SA;
            const float4* vp = (const float4*)(v2e + (size_t)uv * 64) + gh * 8;
            #pragma unroll
            for (int j = 0; j < 8; ++j) {
                float4 f = vp[j];
                float4 g = {tf32f(f.x), tf32f(f.y), tf32f(f.z), tf32f(f.w)};
                *(float4*)&dst[gh * 32 + 4 * j] = g;
            }
            const float4* rp = (const float4*)(r2s + rr * 64) + gh * 8;
            #pragma unroll
            for (int j = 0; j < 8; ++j)
                *(float4*)&dst[64 + gh * 32 + 4 * j] = rp[j];
        }
        __syncthreads();

        // ---- GEMM1: X1 = relu(X @ W1 + b1) -> buf cols 64..127 (over e_r) ----
        CZERO(C);
        gemm_phase<16>(buf, w1p, nh, rbase, lane, C);
        __syncthreads();
        epi_store(buf + 64, C, nh, rbase, lane, b1s);
        __syncthreads();

        // ---- GEMM2: O = relu(X1 @ W2 + b2) -> buf cols 0..63 ; U -> cols 64..127 ----
        CZERO(C);
        gemm_phase<8>(buf + 64, w2p, nh, rbase, lane, C);
        __syncthreads();
        epi_store(buf, C, nh, rbase, lane, b2s);
        {   // stage U over X1
            const float4* up = (const float4*)(ubS + gbs * 64) + gh * 8;
            float* dst = buf + gr * SA + 64;
            #pragma unroll
            for (int j = 0; j < 8; ++j)
                *(float4*)&dst[gh * 32 + 4 * j] = up[j];
        }
        __syncthreads();

        // ---- GEMM3: H1 = relu([O|U] @ A1 + ab1) -> buf cols 64..127 (over U) ----
        CZERO(C);
        gemm_phase<16>(buf, a1p, nh, rbase, lane, C);
        __syncthreads();
        epi_store(buf + 64, C, nh, rbase, lane, ab1s);
        __syncthreads();

        // ---- GEMM4: H2 = relu(H1 @ A2 + ab2); logit partials = H2 . a3 ----
        CZERO(C);
        gemm_phase<8>(buf + 64, a2p, nh, rbase, lane, C);
        {
            const int rq = lane >> 2, q2 = 2 * (lane & 3);
            #pragma unroll
            for (int rg = 0; rg < 2; ++rg) {
                float pa = 0.f, pb = 0.f;
                #pragma unroll
                for (int t = 0; t < 4; ++t) {
                    int c = nh * 32 + t * 8 + q2;
                    pa += fmaxf(C[rg][t][0] + ab2s[c],     0.f) * a3s[c];
                    pa += fmaxf(C[rg][t][1] + ab2s[c + 1], 0.f) * a3s[c + 1];
                    pb += fmaxf(C[rg][t][2] + ab2s[c],     0.f) * a3s[c];
                    pb += fmaxf(C[rg][t][3] + ab2s[c + 1], 0.f) * a3s[c + 1];
                }
                pa += __shfl_xor_sync(~0u, pa, 1); pa += __shfl_xor_sync(~0u, pa, 2);
                pb += __shfl_xor_sync(~0u, pb, 1); pb += __shfl_xor_sync(~0u, pb, 2);
                if ((lane & 3) == 0) {
                    int r0 = rbase + rg * 16 + rq;
                    lgp[nh * 192 + r0]     = pa;
                    lgp[nh * 192 + r0 + 8] = pb;
                }
            }
        }
        __syncthreads();

        // ---- softmax over 50 (warps 0..2 -> b0..b2) ----
        if (tid < 96) {
            int w = tid >> 5, ln2 = tid & 31;
            float v1 = lgp[w * 64 + ln2] + lgp[192 + w * 64 + ln2] + ab3v;
            float v2 = (ln2 + 32 < LN)
                     ? (lgp[w * 64 + ln2 + 32] + lgp[192 + w * 64 + ln2 + 32] + ab3v)
                     : -1e30f;
            float m = fmaxf(v1, v2);
            #pragma unroll
            for (int o = 16; o; o >>= 1) m = fmaxf(m, __shfl_xor_sync(~0u, m, o));
            float e1 = expf(v1 - m);
            float e2 = (ln2 + 32 < LN) ? expf(v2 - m) : 0.f;
            float s = e1 + e2;
            #pragma unroll
            for (int o = 16; o; o >>= 1) s += __shfl_xor_sync(~0u, s, o);
            float inv = 1.f / s;
            att[w * 64 + ln2] = e1 * inv;
            if (ln2 + 32 < LN) att[w * 64 + ln2 + 32] = e2 * inv;
        }
        __syncthreads();

        // ---- aggregation: out[b,d] = sum_l O[l,d]*att[l] (O in buf cols 0..63) ----
        {
            int bs = tid >> 7;                 // 0..2
            int k = tid & 127;
            int d = k & 63, qh = k >> 6;       // qh 0..1
            float acc = 0.f;
            for (int l = qh; l < LN; l += 2)
                acc += buf[(bs * 64 + l) * SA + d] * att[bs * 64 + l];
            red[tid] = acc;
        }
        __syncthreads();
        if (tid < 192) {
            int bs = tid >> 6, d = tid & 63;
            if (b0 + bs < NB)
                out[(size_t)(b0 + bs) * 64 + d] = red[bs * 128 + d] + red[bs * 128 + 64 + d];
        }
        __syncthreads();
    }
}

extern "C" void kernel_launch(void* const* d_in, const int* in_sizes, int n_in,
                              void* d_out, int out_size)
{
    const int*   nodes = (const int*)d_in[0];
    const int*   huv   = (const int*)d_in[1];
    const int*   hr    = (const int*)d_in[2];
    const float* v2e   = (const float*)d_in[3];
    const float* u2e   = (const float*)d_in[4];
    const float* r2e   = (const float*)d_in[5];
    const float* w1    = (const float*)d_in[6];
    const float* b1    = (const float*)d_in[7];
    const float* w2    = (const float*)d_in[8];
    const float* b2    = (const float*)d_in[9];
    const float* a1    = (const float*)d_in[10];
    const float* ab1   = (const float*)d_in[11];
    const float* a2    = (const float*)d_in[12];
    const float* ab2   = (const float*)d_in[13];
    const float* a3    = (const float*)d_in[14];
    const float* ab3   = (const float*)d_in[15];
    float* out = (float*)d_out;

    cudaFuncSetAttribute(uv_agg_mma, cudaFuncAttributeMaxDynamicSharedMemorySize, SMEM_REQ);

    uv_agg_mma<<<148, NTHR, SMEM_REQ>>>(nodes, huv, hr, v2e, u2e, r2e,
                                        w1, b1, w2, b2,
                                        a1, ab1, a2, ab2, a3, ab3, out);
}